// round 1
// baseline (speedup 1.0000x reference)
#include <cuda_runtime.h>
#include <cuda_bf16.h>
#include <math.h>

// Problem dims
#define BB 4
#define TT 1024
#define CC 768
#define HH 12
#define LL 6
#define VV 50257
#define DD 64
#define FF 3072
#define MM (BB*TT)   // 4096 rows

// ---------------- scratch (device globals; allocation-free) ----------------
__device__ float g_h[(size_t)MM*CC];
__device__ float g_x[(size_t)MM*CC];
__device__ float g_q[(size_t)MM*CC];
__device__ float g_k[(size_t)MM*CC];
__device__ float g_v[(size_t)MM*CC];
__device__ float g_o[(size_t)MM*CC];
__device__ float g_m[(size_t)MM*FF];

// ---------------- embedding ----------------
__global__ void embed_kernel(const int* __restrict__ tok,
                             const float* __restrict__ wte,
                             const float* __restrict__ wpe,
                             float* __restrict__ h) {
    int bt = blockIdx.x;
    int t  = bt % TT;
    int tk = tok[bt];
    const float* we = wte + (size_t)tk * CC;
    const float* wp = wpe + (size_t)t  * CC;
    float* hr = h + (size_t)bt * CC;
    for (int c = threadIdx.x; c < CC; c += blockDim.x)
        hr[c] = we[c] + wp[c];
}

// ---------------- layernorm (one block per row) ----------------
__global__ void ln_kernel(const float* __restrict__ x,
                          const float* __restrict__ gamma,
                          const float* __restrict__ beta,
                          float* __restrict__ y) {
    int row = blockIdx.x;
    const float* xr = x + (size_t)row * CC;
    float* yr = y + (size_t)row * CC;
    __shared__ float red[256];
    int tid = threadIdx.x;

    float s = 0.f;
    for (int c = tid; c < CC; c += 256) s += xr[c];
    red[tid] = s; __syncthreads();
    for (int o = 128; o > 0; o >>= 1) {
        if (tid < o) red[tid] += red[tid + o];
        __syncthreads();
    }
    float mu = red[0] * (1.0f / CC);
    __syncthreads();

    float v = 0.f;
    for (int c = tid; c < CC; c += 256) { float d = xr[c] - mu; v += d * d; }
    red[tid] = v; __syncthreads();
    for (int o = 128; o > 0; o >>= 1) {
        if (tid < o) red[tid] += red[tid + o];
        __syncthreads();
    }
    float rstd = rsqrtf(red[0] * (1.0f / CC) + 1e-5f);

    for (int c = tid; c < CC; c += 256)
        yr[c] = (xr[c] - mu) * rstd * gamma[c] + beta[c];
}

// ---------------- generic tiled SGEMM with fused epilogue ----------------
// C[M,N] = epilogue(A[M,K] @ Bm[K,N])
// EPI: 0 = none, 1 = +bias, 2 = gelu(+bias), 3 = residual + bias + acc
#define EPI_NONE 0
#define EPI_BIAS 1
#define EPI_BIAS_GELU 2
#define EPI_BIAS_RES 3

template<int EPI>
__global__ __launch_bounds__(256)
void sgemm_kernel(const float* __restrict__ A,
                  const float* __restrict__ Bm,
                  const float* __restrict__ bias,
                  const float* __restrict__ Res,
                  float* __restrict__ Cc,
                  int M, int N, int K) {
    const int BMt = 128, BNt = 128, BKt = 16;
    __shared__ float As[BKt][132];      // transposed A tile, padded
    __shared__ float Bs[BKt][BNt];

    int tid = threadIdx.x;
    int tx = tid & 15;          // col group
    int ty = tid >> 4;          // row group
    int row0 = blockIdx.y * BMt;
    int col0 = blockIdx.x * BNt;

    const bool vecB = ((N & 3) == 0) && (col0 + BNt <= N);

    float acc[8][8];
#pragma unroll
    for (int i = 0; i < 8; i++)
#pragma unroll
        for (int j = 0; j < 8; j++) acc[i][j] = 0.f;

    for (int k0 = 0; k0 < K; k0 += BKt) {
        // load A tile (BM x BK), store transposed.  512 float4 by 256 threads.
#pragma unroll
        for (int it = 0; it < 2; it++) {
            int v = tid + it * 256;
            int r  = v >> 2;
            int cv = (v & 3) << 2;
            float4 a4 = *(const float4*)(A + (size_t)(row0 + r) * K + k0 + cv);
            As[cv + 0][r] = a4.x;
            As[cv + 1][r] = a4.y;
            As[cv + 2][r] = a4.z;
            As[cv + 3][r] = a4.w;
        }
        // load B tile (BK x BN)
        if (vecB) {
#pragma unroll
            for (int it = 0; it < 2; it++) {
                int v = tid + it * 256;
                int r  = v >> 5;
                int cv = (v & 31) << 2;
                *(float4*)&Bs[r][cv] =
                    *(const float4*)(Bm + (size_t)(k0 + r) * N + col0 + cv);
            }
        } else {
#pragma unroll
            for (int it = 0; it < 8; it++) {
                int e = tid + it * 256;
                int r = e >> 7;
                int c = e & 127;
                int gc = col0 + c;
                Bs[r][c] = (gc < N) ? Bm[(size_t)(k0 + r) * N + gc] : 0.f;
            }
        }
        __syncthreads();

#pragma unroll
        for (int kk = 0; kk < BKt; kk++) {
            float a[8], b[8];
            *(float4*)&a[0] = *(float4*)&As[kk][ty * 8];
            *(float4*)&a[4] = *(float4*)&As[kk][ty * 8 + 4];
            *(float4*)&b[0] = *(float4*)&Bs[kk][tx * 8];
            *(float4*)&b[4] = *(float4*)&Bs[kk][tx * 8 + 4];
#pragma unroll
            for (int i = 0; i < 8; i++)
#pragma unroll
                for (int j = 0; j < 8; j++)
                    acc[i][j] = fmaf(a[i], b[j], acc[i][j]);
        }
        __syncthreads();
    }

#pragma unroll
    for (int i = 0; i < 8; i++) {
        int row = row0 + ty * 8 + i;
#pragma unroll
        for (int j = 0; j < 8; j++) {
            int col = col0 + tx * 8 + j;
            if (col < N) {
                float v = acc[i][j];
                size_t idx = (size_t)row * N + col;
                if (EPI == EPI_BIAS) {
                    v += bias[col];
                } else if (EPI == EPI_BIAS_GELU) {
                    v += bias[col];
                    v = 0.5f * v * (1.0f + erff(v * 0.7071067811865476f));
                } else if (EPI == EPI_BIAS_RES) {
                    v += bias[col] + Res[idx];
                }
                Cc[idx] = v;
            }
        }
    }
}

// ---------------- fused causal attention ----------------
// grid (T, H, B), block 64 threads. Thread d owns output dim d.
__global__ __launch_bounds__(64)
void attn_kernel(const float* __restrict__ Q,
                 const float* __restrict__ K,
                 const float* __restrict__ V,
                 float* __restrict__ O) {
    int qi = blockIdx.x;
    int hh = blockIdx.y;
    int b  = blockIdx.z;
    int d  = threadIdx.x;

    __shared__ float sq[64];
    __shared__ float ss[64];
    __shared__ float sk[64][65];   // padded: conflict-free row dots

    const float scale = rsqrtf((float)CC);
    size_t qoff = ((size_t)(b * TT + qi)) * CC + hh * DD + d;
    sq[d] = Q[qoff];
    __syncthreads();

    float m = -INFINITY, l = 0.f, acc = 0.f;

    for (int j0 = 0; j0 <= qi; j0 += 64) {
        int jn = min(64, qi + 1 - j0);
        // stage K tile into shared (coalesced)
        for (int idx = d; idx < jn * 64; idx += 64) {
            int r = idx >> 6, c = idx & 63;
            sk[r][c] = K[((size_t)(b * TT + j0 + r)) * CC + hh * DD + c];
        }
        __syncthreads();

        if (d < jn) {
            const float* kr = sk[d];
            float s = 0.f;
#pragma unroll
            for (int u = 0; u < 64; u++) s = fmaf(sq[u], kr[u], s);
            ss[d] = s * scale;
        }
        __syncthreads();

        float tmax = -INFINITY;
        for (int j = 0; j < jn; j++) tmax = fmaxf(tmax, ss[j]);
        float newm = fmaxf(m, tmax);
        float corr = expf(m - newm);
        acc *= corr;
        l   *= corr;
        for (int j = 0; j < jn; j++) {
            float p = expf(ss[j] - newm);
            l += p;
            acc = fmaf(p, V[((size_t)(b * TT + j0 + j)) * CC + hh * DD + d], acc);
        }
        m = newm;
        __syncthreads();
    }

    O[qoff] = acc / l;
}

// ---------------- launch ----------------
extern "C" void kernel_launch(void* const* d_in, const int* in_sizes, int n_in,
                              void* d_out, int out_size) {
    const int*   tokens = (const int*)  d_in[0];
    const float* wte    = (const float*)d_in[1];
    const float* wpe    = (const float*)d_in[2];
    const float* Wq     = (const float*)d_in[3];
    const float* Wk     = (const float*)d_in[4];
    const float* Wv     = (const float*)d_in[5];
    const float* Wo     = (const float*)d_in[6];
    const float* bo     = (const float*)d_in[7];
    const float* ln1g   = (const float*)d_in[8];
    const float* ln1b   = (const float*)d_in[9];
    const float* ln2g   = (const float*)d_in[10];
    const float* ln2b   = (const float*)d_in[11];
    const float* W1     = (const float*)d_in[12];
    const float* b1     = (const float*)d_in[13];
    const float* W2     = (const float*)d_in[14];
    const float* b2     = (const float*)d_in[15];
    const float* lnfg   = (const float*)d_in[16];
    const float* lnfb   = (const float*)d_in[17];
    const float* Wh     = (const float*)d_in[18];
    const float* bh     = (const float*)d_in[19];
    float* out = (float*)d_out;

    float *h, *x, *q, *k, *v, *o, *mbuf;
    cudaGetSymbolAddress((void**)&h,    g_h);
    cudaGetSymbolAddress((void**)&x,    g_x);
    cudaGetSymbolAddress((void**)&q,    g_q);
    cudaGetSymbolAddress((void**)&k,    g_k);
    cudaGetSymbolAddress((void**)&v,    g_v);
    cudaGetSymbolAddress((void**)&o,    g_o);
    cudaGetSymbolAddress((void**)&mbuf, g_m);

    dim3 gC((CC + 127) / 128, MM / 128);   // N = 768
    dim3 gF((FF + 127) / 128, MM / 128);   // N = 3072
    dim3 gV((VV + 127) / 128, MM / 128);   // N = 50257

    embed_kernel<<<MM, 256>>>(tokens, wte, wpe, h);

    for (int l = 0; l < LL; l++) {
        const float* wql = Wq + (size_t)l * CC * CC;
        const float* wkl = Wk + (size_t)l * CC * CC;
        const float* wvl = Wv + (size_t)l * CC * CC;
        const float* wol = Wo + (size_t)l * CC * CC;
        const float* w1l = W1 + (size_t)l * CC * FF;
        const float* w2l = W2 + (size_t)l * FF * CC;

        ln_kernel<<<MM, 256>>>(h, ln1g + l * CC, ln1b + l * CC, x);
        sgemm_kernel<EPI_NONE><<<gC, 256>>>(x, wql, nullptr, nullptr, q, MM, CC, CC);
        sgemm_kernel<EPI_NONE><<<gC, 256>>>(x, wkl, nullptr, nullptr, k, MM, CC, CC);
        sgemm_kernel<EPI_NONE><<<gC, 256>>>(x, wvl, nullptr, nullptr, v, MM, CC, CC);

        attn_kernel<<<dim3(TT, HH, BB), 64>>>(q, k, v, o);

        sgemm_kernel<EPI_BIAS_RES><<<gC, 256>>>(o, wol, bo + l * CC, h, h, MM, CC, CC);

        ln_kernel<<<MM, 256>>>(h, ln2g + l * CC, ln2b + l * CC, x);
        sgemm_kernel<EPI_BIAS_GELU><<<gF, 256>>>(x, w1l, b1 + l * FF, nullptr, mbuf, MM, FF, CC);
        sgemm_kernel<EPI_BIAS_RES><<<gC, 256>>>(mbuf, w2l, b2 + l * CC, h, h, MM, CC, FF);
    }

    ln_kernel<<<MM, 256>>>(h, lnfg, lnfb, x);
    sgemm_kernel<EPI_BIAS><<<gV, 256>>>(x, Wh, bh, nullptr, out, MM, VV, CC);
}

// round 4
// speedup vs baseline: 2.1145x; 2.1145x over previous
#include <cuda_runtime.h>
#include <cuda_bf16.h>
#include <math.h>
#include <stdint.h>

// Problem dims
#define BB 4
#define TT 1024
#define CC 768
#define HH 12
#define LL 6
#define VV 50257
#define DD 64
#define FF 3072
#define MM (BB*TT)        // 4096 rows
#define NQKV 2304
#define VPAD 50304        // 393*128

// ---------------- scratch (device globals; allocation-free) ----------------
__device__ float g_h[(size_t)MM*CC];
__device__ float g_qkv[(size_t)MM*NQKV];
// packed bf16 hi/lo operand buffers: layout [blk128][K/64][r:128][pl:2][64]
__device__ __align__(256) __nv_bfloat16 g_xpk [(size_t)MM*CC*2];
__device__ __align__(256) __nv_bfloat16 g_opk [(size_t)MM*CC*2];
__device__ __align__(256) __nv_bfloat16 g_mpk [(size_t)MM*FF*2];
__device__ __align__(256) __nv_bfloat16 g_wqkvpk[(size_t)NQKV*CC*2];
__device__ __align__(256) __nv_bfloat16 g_wopk  [(size_t)CC*CC*2];
__device__ __align__(256) __nv_bfloat16 g_w1pk  [(size_t)FF*CC*2];
__device__ __align__(256) __nv_bfloat16 g_w2pk  [(size_t)CC*FF*2];
__device__ __align__(256) __nv_bfloat16 g_whpk  [(size_t)VPAD*CC*2];

// ======================= PTX helpers (sm_90 baseline only) =======================
__device__ __forceinline__ uint32_t smem_u32(const void* p) {
    uint32_t a;
    asm("{ .reg .u64 t; cvta.to.shared.u64 t, %1; cvt.u32.u64 %0, t; }"
        : "=r"(a) : "l"(p));
    return a;
}
#define MBAR_INIT(addr, cnt) \
    asm volatile("mbarrier.init.shared.b64 [%0], %1;" :: "r"(addr), "r"((uint32_t)(cnt)) : "memory")
#define MBAR_EXPECT_TX(addr, bytes) \
    asm volatile("mbarrier.arrive.expect_tx.shared.b64 _, [%0], %1;" \
                 :: "r"(addr), "r"((uint32_t)(bytes)) : "memory")

__device__ __forceinline__ void mbar_wait(uint32_t mbar, uint32_t parity) {
    uint32_t done;
    asm volatile(
        "{\n\t.reg .pred p;\n\t"
        "mbarrier.try_wait.parity.acquire.cta.shared::cta.b64 p, [%1], %2;\n\t"
        "selp.b32 %0, 1, 0, p;\n\t}"
        : "=r"(done) : "r"(mbar), "r"(parity) : "memory");
    if (!done) {
        asm volatile(
            "{\n\t.reg .pred P1;\n\t"
            "WAIT_LOOP_%=:\n\t"
            "mbarrier.try_wait.parity.acquire.cta.shared::cta.b64 P1, [%0], %1, 0x989680;\n\t"
            "@P1 bra.uni WAIT_DONE_%=;\n\t"
            "bra.uni WAIT_LOOP_%=;\n\t"
            "WAIT_DONE_%=:\n\t}"
            :: "r"(mbar), "r"(parity) : "memory");
    }
}
__device__ __forceinline__ void bulk_g2s(uint32_t dst, const void* src,
                                         uint32_t bytes, uint32_t mbar) {
    asm volatile(
        "cp.async.bulk.shared::cluster.global.mbarrier::complete_tx::bytes "
        "[%0], [%1], %2, [%3];"
        :: "r"(dst), "l"(src), "r"(bytes), "r"(mbar) : "memory");
}
__device__ __forceinline__ void ldsm4(uint32_t* r, uint32_t addr) {
    asm volatile("ldmatrix.sync.aligned.m8n8.x4.shared.b16 {%0,%1,%2,%3}, [%4];"
        : "=r"(r[0]), "=r"(r[1]), "=r"(r[2]), "=r"(r[3]) : "r"(addr));
}
__device__ __forceinline__ void mma16816(float* d, const uint32_t* a, const uint32_t* b) {
    asm volatile(
        "mma.sync.aligned.m16n8k16.row.col.f32.bf16.bf16.f32 "
        "{%0,%1,%2,%3}, {%4,%5,%6,%7}, {%8,%9}, {%0,%1,%2,%3};"
        : "+f"(d[0]), "+f"(d[1]), "+f"(d[2]), "+f"(d[3])
        : "r"(a[0]), "r"(a[1]), "r"(a[2]), "r"(a[3]), "r"(b[0]), "r"(b[1]));
}

// packed layout helper: element index for (blk128, kc, r, pl, kk)
// idx = ((blk*KC + kc)*128 + r)*128 + pl*64 + ((ch ^ (r&7))*8 + w8)
__device__ __forceinline__ size_t pk_rowseg(int KC, int blk, int kc, int r) {
    return ((size_t)(blk * KC + kc) * 128 + r) * 128;
}
__device__ __forceinline__ int pk_within(int r, int kk) {
    int ch = kk >> 3, w8 = kk & 7;
    return ((ch ^ (r & 7)) << 3) + w8;
}

// ======================= small kernels =======================
__global__ void embed_kernel(const int* __restrict__ tok,
                             const float* __restrict__ wte,
                             const float* __restrict__ wpe,
                             float* __restrict__ h) {
    int bt = blockIdx.x;
    int t  = bt % TT;
    int tk = tok[bt];
    const float* we = wte + (size_t)tk * CC;
    const float* wp = wpe + (size_t)t  * CC;
    float* hr = h + (size_t)bt * CC;
    for (int c = threadIdx.x; c < CC; c += blockDim.x)
        hr[c] = we[c] + wp[c];
}

// LayerNorm producing packed bf16 hi/lo A-operand (KC = CC/64 = 12)
__global__ void ln_pk_kernel(const float* __restrict__ x,
                             const float* __restrict__ gamma,
                             const float* __restrict__ beta,
                             __nv_bfloat16* __restrict__ outpk) {
    int row = blockIdx.x;
    const float* xr = x + (size_t)row * CC;
    __shared__ float red[256];
    int tid = threadIdx.x;

    float s = 0.f;
    for (int c = tid; c < CC; c += 256) s += xr[c];
    red[tid] = s; __syncthreads();
    for (int o = 128; o > 0; o >>= 1) {
        if (tid < o) red[tid] += red[tid + o];
        __syncthreads();
    }
    float mu = red[0] * (1.0f / CC);
    __syncthreads();

    float v = 0.f;
    for (int c = tid; c < CC; c += 256) { float d = xr[c] - mu; v += d * d; }
    red[tid] = v; __syncthreads();
    for (int o = 128; o > 0; o >>= 1) {
        if (tid < o) red[tid] += red[tid + o];
        __syncthreads();
    }
    float rstd = rsqrtf(red[0] * (1.0f / CC) + 1e-5f);

    int blk = row >> 7, r = row & 127;
    for (int c = tid; c < CC; c += 256) {
        float val = (xr[c] - mu) * rstd * gamma[c] + beta[c];
        __nv_bfloat16 hi = __float2bfloat16(val);
        __nv_bfloat16 lo = __float2bfloat16(val - __bfloat162float(hi));
        size_t base = pk_rowseg(12, blk, c >> 6, r);
        int w = pk_within(r, c & 63);
        outpk[base + w]      = hi;
        outpk[base + 64 + w] = lo;
    }
}

// transpose + convert + split weight W[K,N](fp32) -> packed [n-blocks][K/64][...]
// one block per (n-tile 64, k-tile 64); n0out shifts output rows (for QKV concat)
__global__ __launch_bounds__(256)
void pack_w_kernel(const float* __restrict__ W, __nv_bfloat16* __restrict__ Bpk,
                   int K, int N, int n0out) {
    __shared__ float sm[64][65];
    int tid = threadIdx.x;
    int n0 = blockIdx.x * 64;
    int k0 = blockIdx.y * 64;
    int KC = K >> 6;

    for (int idx = tid; idx < 64 * 64; idx += 256) {
        int kr = idx >> 6, nc = idx & 63;
        int gn = n0 + nc;
        sm[kr][nc] = (gn < N) ? W[(size_t)(k0 + kr) * N + gn] : 0.f;
    }
    __syncthreads();

    for (int g = tid; g < 512; g += 256) {
        int n = g >> 3, ch = g & 7;
        int gn = n0out + n0 + n;
        int bn = gn >> 7, r = gn & 127;
        size_t base = pk_rowseg(KC, bn, blockIdx.y, r);
        int w = (ch ^ (r & 7)) << 3;
        union { uint4 v; __nv_bfloat16 b[8]; } uh, ul;
#pragma unroll
        for (int j = 0; j < 8; ++j) {
            float x = sm[ch * 8 + j][n];
            __nv_bfloat16 hi = __float2bfloat16(x);
            uh.b[j] = hi;
            ul.b[j] = __float2bfloat16(x - __bfloat162float(hi));
        }
        *(uint4*)(Bpk + base + w)      = uh.v;
        *(uint4*)(Bpk + base + 64 + w) = ul.v;
    }
}

// ======================= HMMA GEMM (mma.sync bf16 x3 split) =======================
// C[M,N] = epi(A[M,K] @ B^T), A/B in packed bf16 hi/lo swizzled layout.
#define EPI_NONE 0
#define EPI_BIAS 1
#define EPI_GELU_PK 2
#define EPI_RES 3

#define STAGES 3
#define STAGE_BYTES 65536   // A 32K | B 32K  (BK=64)
#define HG_SMEM (STAGES * STAGE_BYTES)

template<int EPI>
__global__ __launch_bounds__(256, 1)
void hgemm(const __nv_bfloat16* __restrict__ Apk,
           const __nv_bfloat16* __restrict__ Bpk,
           const float* __restrict__ bias,
           const float* __restrict__ Res,
           float* __restrict__ outf,
           __nv_bfloat16* __restrict__ outpk,
           int N, int K, int Nl) {
    extern __shared__ __align__(1024) char smem[];
    __shared__ __align__(8) uint64_t s_full[STAGES];

    int tid = threadIdx.x;
    int lane = tid & 31, w = tid >> 5;
    int wm = w & 1, wn = w >> 1;      // warp grid 2(M) x 4(N)
    int bm = blockIdx.y, bn = blockIdx.x;
    int KC = K >> 6;
    uint32_t sbase = smem_u32(smem);
    uint32_t mb0 = smem_u32(&s_full[0]);

    if (tid == 0) {
#pragma unroll
        for (int s = 0; s < STAGES; ++s) MBAR_INIT(mb0 + s * 8, 1);
    }
    __syncthreads();

    float acc[4][4][4];
#pragma unroll
    for (int i = 0; i < 4; ++i)
#pragma unroll
        for (int j = 0; j < 4; ++j)
#pragma unroll
            for (int q = 0; q < 4; ++q) acc[i][j][q] = 0.f;

    const int la15 = lane & 15, lahi = lane >> 4;
    const int bmx = lane >> 3;
    const int brow_base = wn * 32 + ((bmx >> 1) << 3) + (lane & 7);
    const int bcs = bmx & 1;

    const int nc = KC;
    const size_t CHUNK = 16384;   // bf16 elements per 32KB block

    if (tid == 0) {
#pragma unroll
        for (int c = 0; c < STAGES - 1; ++c) {
            uint32_t m = mb0 + c * 8;
            MBAR_EXPECT_TX(m, STAGE_BYTES);
            bulk_g2s(sbase + c * STAGE_BYTES,
                     Apk + ((size_t)bm * KC + c) * CHUNK, 32768, m);
            bulk_g2s(sbase + c * STAGE_BYTES + 32768,
                     Bpk + ((size_t)bn * KC + c) * CHUNK, 32768, m);
        }
    }

    for (int c = 0; c < nc; ++c) {
        int s = c % STAGES;
        mbar_wait(mb0 + s * 8, (c / STAGES) & 1);

        if (tid == 0) {
            int cn = c + STAGES - 1;
            if (cn < nc) {
                int sn = cn % STAGES;
                uint32_t m = mb0 + sn * 8;
                MBAR_EXPECT_TX(m, STAGE_BYTES);
                bulk_g2s(sbase + sn * STAGE_BYTES,
                         Apk + ((size_t)bm * KC + cn) * CHUNK, 32768, m);
                bulk_g2s(sbase + sn * STAGE_BYTES + 32768,
                         Bpk + ((size_t)bn * KC + cn) * CHUNK, 32768, m);
            }
        }

        uint32_t Ab = sbase + s * STAGE_BYTES;
        uint32_t Bb = Ab + 32768;

#pragma unroll
        for (int kh = 0; kh < 4; ++kh) {
            uint32_t af[2][4][4];
            uint32_t bf_[2][4][2];
#pragma unroll
            for (int im = 0; im < 4; ++im) {
                int r = wm * 64 + im * 16 + la15;
                int cch = kh * 2 + lahi;
                uint32_t off = (uint32_t)(r * 256 + (((cch ^ (r & 7))) << 4));
                ldsm4(af[0][im], Ab + off);
                ldsm4(af[1][im], Ab + off + 128);
            }
#pragma unroll
            for (int g2 = 0; g2 < 2; ++g2) {
                int nr = brow_base + g2 * 16;
                int cch = kh * 2 + bcs;
                uint32_t off = (uint32_t)(nr * 256 + (((cch ^ (nr & 7))) << 4));
#pragma unroll
                for (int pl = 0; pl < 2; ++pl) {
                    uint32_t t4[4];
                    ldsm4(t4, Bb + off + pl * 128);
                    bf_[pl][g2 * 2][0]     = t4[0];
                    bf_[pl][g2 * 2][1]     = t4[1];
                    bf_[pl][g2 * 2 + 1][0] = t4[2];
                    bf_[pl][g2 * 2 + 1][1] = t4[3];
                }
            }
#pragma unroll
            for (int im = 0; im < 4; ++im)
#pragma unroll
                for (int in_ = 0; in_ < 4; ++in_) {
                    mma16816(acc[im][in_], af[0][im], bf_[0][in_]);
                    mma16816(acc[im][in_], af[0][im], bf_[1][in_]);
                    mma16816(acc[im][in_], af[1][im], bf_[0][in_]);
                }
        }
        __syncthreads();
    }

    // ---------------- epilogue ----------------
    int r0 = bm * 128 + wm * 64 + (lane >> 2);
    int c0base = bn * 128 + wn * 32 + 2 * (lane & 3);
    int KCo = N >> 6;   // for packed out

#pragma unroll
    for (int im = 0; im < 4; ++im) {
#pragma unroll
        for (int half = 0; half < 2; ++half) {
            int row = r0 + im * 16 + half * 8;
#pragma unroll
            for (int in_ = 0; in_ < 4; ++in_) {
                int col = c0base + in_ * 8;
                float v0 = acc[im][in_][half * 2 + 0];
                float v1 = acc[im][in_][half * 2 + 1];
                if (EPI == EPI_NONE) {
                    *(float2*)(outf + (size_t)row * Nl + col) = make_float2(v0, v1);
                } else if (EPI == EPI_RES) {
                    const float* rr = Res + (size_t)row * Nl + col;
                    v0 += bias[col]     + rr[0];
                    v1 += bias[col + 1] + rr[1];
                    *(float2*)(outf + (size_t)row * Nl + col) = make_float2(v0, v1);
                } else if (EPI == EPI_BIAS) {
                    if (col < Nl)     outf[(size_t)row * Nl + col]     = v0 + bias[col];
                    if (col + 1 < Nl) outf[(size_t)row * Nl + col + 1] = v1 + bias[col + 1];
                } else if (EPI == EPI_GELU_PK) {
                    v0 += bias[col];
                    v1 += bias[col + 1];
                    v0 = 0.5f * v0 * (1.0f + erff(v0 * 0.7071067811865476f));
                    v1 = 0.5f * v1 * (1.0f + erff(v1 * 0.7071067811865476f));
                    __nv_bfloat16 h0 = __float2bfloat16(v0);
                    __nv_bfloat16 h1 = __float2bfloat16(v1);
                    __nv_bfloat16 l0 = __float2bfloat16(v0 - __bfloat162float(h0));
                    __nv_bfloat16 l1 = __float2bfloat16(v1 - __bfloat162float(h1));
                    int blk = row >> 7, r = row & 127;
                    size_t base = pk_rowseg(KCo, blk, col >> 6, r);
                    int wi = pk_within(r, col & 63);
                    *(__nv_bfloat162*)(outpk + base + wi) =
                        __nv_bfloat162(h0, h1);
                    *(__nv_bfloat162*)(outpk + base + 64 + wi) =
                        __nv_bfloat162(l0, l1);
                }
            }
        }
    }
}

// ---------------- fused causal attention (fp32, qkv combined) ----------------
__global__ __launch_bounds__(64)
void attn_kernel(const float* __restrict__ QKV,
                 __nv_bfloat16* __restrict__ Opk) {
    int qi = blockIdx.x;
    int hh = blockIdx.y;
    int b  = blockIdx.z;
    int d  = threadIdx.x;

    __shared__ float sq[64];
    __shared__ float ss[64];
    __shared__ float sk[64][65];

    const float scale = rsqrtf((float)CC);
    int row = b * TT + qi;
    size_t qoff = (size_t)row * NQKV + hh * DD + d;
    sq[d] = QKV[qoff];
    __syncthreads();

    float m = -INFINITY, l = 0.f, acc = 0.f;

    for (int j0 = 0; j0 <= qi; j0 += 64) {
        int jn = min(64, qi + 1 - j0);
        for (int idx = d; idx < jn * 64; idx += 64) {
            int r = idx >> 6, c = idx & 63;
            sk[r][c] = QKV[((size_t)(b * TT + j0 + r)) * NQKV + CC + hh * DD + c];
        }
        __syncthreads();

        if (d < jn) {
            const float* kr = sk[d];
            float s = 0.f;
#pragma unroll
            for (int u = 0; u < 64; u++) s = fmaf(sq[u], kr[u], s);
            ss[d] = s * scale;
        }
        __syncthreads();

        float tmax = -INFINITY;
        for (int j = 0; j < jn; j++) tmax = fmaxf(tmax, ss[j]);
        float newm = fmaxf(m, tmax);
        float corr = expf(m - newm);
        acc *= corr;
        l   *= corr;
        for (int j = 0; j < jn; j++) {
            float p = expf(ss[j] - newm);
            l += p;
            acc = fmaf(p, QKV[((size_t)(b * TT + j0 + j)) * NQKV + 2 * CC + hh * DD + d], acc);
        }
        m = newm;
        __syncthreads();
    }

    float val = acc / l;
    __nv_bfloat16 hi = __float2bfloat16(val);
    __nv_bfloat16 lo = __float2bfloat16(val - __bfloat162float(hi));
    int blk = row >> 7, r = row & 127;
    size_t base = pk_rowseg(12, blk, hh, r);   // DD==64 so kc == hh
    int wi = pk_within(r, d);
    Opk[base + wi]      = hi;
    Opk[base + 64 + wi] = lo;
}

// ======================= launch =======================
extern "C" void kernel_launch(void* const* d_in, const int* in_sizes, int n_in,
                              void* d_out, int out_size) {
    const int*   tokens = (const int*)  d_in[0];
    const float* wte    = (const float*)d_in[1];
    const float* wpe    = (const float*)d_in[2];
    const float* Wq     = (const float*)d_in[3];
    const float* Wk     = (const float*)d_in[4];
    const float* Wv     = (const float*)d_in[5];
    const float* Wo     = (const float*)d_in[6];
    const float* bo     = (const float*)d_in[7];
    const float* ln1g   = (const float*)d_in[8];
    const float* ln1b   = (const float*)d_in[9];
    const float* ln2g   = (const float*)d_in[10];
    const float* ln2b   = (const float*)d_in[11];
    const float* W1     = (const float*)d_in[12];
    const float* b1     = (const float*)d_in[13];
    const float* W2     = (const float*)d_in[14];
    const float* b2     = (const float*)d_in[15];
    const float* lnfg   = (const float*)d_in[16];
    const float* lnfb   = (const float*)d_in[17];
    const float* Wh     = (const float*)d_in[18];
    const float* bh     = (const float*)d_in[19];
    float* out = (float*)d_out;

    static bool attrs_set = false;
    if (!attrs_set) {
        cudaFuncSetAttribute(hgemm<EPI_NONE>,    cudaFuncAttributeMaxDynamicSharedMemorySize, HG_SMEM);
        cudaFuncSetAttribute(hgemm<EPI_BIAS>,    cudaFuncAttributeMaxDynamicSharedMemorySize, HG_SMEM);
        cudaFuncSetAttribute(hgemm<EPI_GELU_PK>, cudaFuncAttributeMaxDynamicSharedMemorySize, HG_SMEM);
        cudaFuncSetAttribute(hgemm<EPI_RES>,     cudaFuncAttributeMaxDynamicSharedMemorySize, HG_SMEM);
        attrs_set = true;
    }

    float *h, *qkv;
    __nv_bfloat16 *xpk, *opk, *mpk, *wqkvpk, *wopk, *w1pk, *w2pk, *whpk;
    cudaGetSymbolAddress((void**)&h,      g_h);
    cudaGetSymbolAddress((void**)&qkv,    g_qkv);
    cudaGetSymbolAddress((void**)&xpk,    g_xpk);
    cudaGetSymbolAddress((void**)&opk,    g_opk);
    cudaGetSymbolAddress((void**)&mpk,    g_mpk);
    cudaGetSymbolAddress((void**)&wqkvpk, g_wqkvpk);
    cudaGetSymbolAddress((void**)&wopk,   g_wopk);
    cudaGetSymbolAddress((void**)&w1pk,   g_w1pk);
    cudaGetSymbolAddress((void**)&w2pk,   g_w2pk);
    cudaGetSymbolAddress((void**)&whpk,   g_whpk);

    dim3 gQKV(NQKV / 128, MM / 128);   // (18, 32)
    dim3 gC(CC / 128, MM / 128);       // (6, 32)
    dim3 gF(FF / 128, MM / 128);       // (24, 32)
    dim3 gV(VPAD / 128, MM / 128);     // (393, 32)

    // pack grids: (N/64 tiles, K/64 tiles)
    dim3 pCC(12, 12);       // 768x768
    dim3 pW1(48, 12);       // K=768, N=3072
    dim3 pW2(12, 48);       // K=3072, N=768
    dim3 pWh(786, 12);      // K=768, N=50257 (padded to 50304)

    embed_kernel<<<MM, 256>>>(tokens, wte, wpe, h);
    pack_w_kernel<<<pWh, 256>>>(Wh, whpk, CC, VV, 0);

    for (int l = 0; l < LL; l++) {
        pack_w_kernel<<<pCC, 256>>>(Wq + (size_t)l * CC * CC, wqkvpk, CC, CC, 0);
        pack_w_kernel<<<pCC, 256>>>(Wk + (size_t)l * CC * CC, wqkvpk, CC, CC, 768);
        pack_w_kernel<<<pCC, 256>>>(Wv + (size_t)l * CC * CC, wqkvpk, CC, CC, 1536);
        pack_w_kernel<<<pCC, 256>>>(Wo + (size_t)l * CC * CC, wopk, CC, CC, 0);
        pack_w_kernel<<<pW1, 256>>>(W1 + (size_t)l * CC * FF, w1pk, CC, FF, 0);
        pack_w_kernel<<<pW2, 256>>>(W2 + (size_t)l * FF * CC, w2pk, FF, CC, 0);

        ln_pk_kernel<<<MM, 256>>>(h, ln1g + l * CC, ln1b + l * CC, xpk);
        hgemm<EPI_NONE><<<gQKV, 256, HG_SMEM>>>(xpk, wqkvpk, nullptr, nullptr,
                                                qkv, nullptr, NQKV, CC, NQKV);

        attn_kernel<<<dim3(TT, HH, BB), 64>>>(qkv, opk);

        hgemm<EPI_RES><<<gC, 256, HG_SMEM>>>(opk, wopk, bo + l * CC, h,
                                             h, nullptr, CC, CC, CC);

        ln_pk_kernel<<<MM, 256>>>(h, ln2g + l * CC, ln2b + l * CC, xpk);
        hgemm<EPI_GELU_PK><<<gF, 256, HG_SMEM>>>(xpk, w1pk, b1 + l * FF, nullptr,
                                                 nullptr, mpk, FF, CC, FF);
        hgemm<EPI_RES><<<gC, 256, HG_SMEM>>>(mpk, w2pk, b2 + l * CC, h,
                                             h, nullptr, CC, FF, CC);
    }

    ln_pk_kernel<<<MM, 256>>>(h, lnfg, lnfb, xpk);
    hgemm<EPI_BIAS><<<gV, 256, HG_SMEM>>>(xpk, whpk, bh, nullptr,
                                          out, nullptr, VPAD, CC, VV);
}

// round 6
// speedup vs baseline: 3.2500x; 1.5370x over previous
#include <cuda_runtime.h>
#include <cuda_bf16.h>
#include <math.h>
#include <stdint.h>

// Problem dims
#define BB 4
#define TT 1024
#define CC 768
#define HH 12
#define LL 6
#define VV 50257
#define DD 64
#define FF 3072
#define MM (BB*TT)        // 4096 rows
#define NQKV 2304
#define VPAD 50304        // 393*128

// ---------------- scratch (device globals; allocation-free) ----------------
__device__ float g_h[(size_t)MM*CC];
__device__ float g_qkv[(size_t)MM*NQKV];
// packed bf16 hi/lo operand buffers: layout [blk128][K/64][r:128][pl:2][64]
__device__ __align__(256) __nv_bfloat16 g_xpk [(size_t)MM*CC*2];
__device__ __align__(256) __nv_bfloat16 g_opk [(size_t)MM*CC*2];
__device__ __align__(256) __nv_bfloat16 g_mpk [(size_t)MM*FF*2];
__device__ __align__(256) __nv_bfloat16 g_wqkvpk[(size_t)NQKV*CC*2];
__device__ __align__(256) __nv_bfloat16 g_wopk  [(size_t)CC*CC*2];
__device__ __align__(256) __nv_bfloat16 g_w1pk  [(size_t)FF*CC*2];
__device__ __align__(256) __nv_bfloat16 g_w2pk  [(size_t)CC*FF*2];
__device__ __align__(256) __nv_bfloat16 g_whpk  [(size_t)VPAD*CC*2];

// ======================= PTX helpers (sm_90 baseline only) =======================
__device__ __forceinline__ uint32_t smem_u32(const void* p) {
    uint32_t a;
    asm("{ .reg .u64 t; cvta.to.shared.u64 t, %1; cvt.u32.u64 %0, t; }"
        : "=r"(a) : "l"(p));
    return a;
}
#define MBAR_INIT(addr, cnt) \
    asm volatile("mbarrier.init.shared.b64 [%0], %1;" :: "r"(addr), "r"((uint32_t)(cnt)) : "memory")
#define MBAR_EXPECT_TX(addr, bytes) \
    asm volatile("mbarrier.arrive.expect_tx.shared.b64 _, [%0], %1;" \
                 :: "r"(addr), "r"((uint32_t)(bytes)) : "memory")

__device__ __forceinline__ void mbar_wait(uint32_t mbar, uint32_t parity) {
    uint32_t done;
    asm volatile(
        "{\n\t.reg .pred p;\n\t"
        "mbarrier.try_wait.parity.acquire.cta.shared::cta.b64 p, [%1], %2;\n\t"
        "selp.b32 %0, 1, 0, p;\n\t}"
        : "=r"(done) : "r"(mbar), "r"(parity) : "memory");
    if (!done) {
        asm volatile(
            "{\n\t.reg .pred P1;\n\t"
            "WAIT_LOOP_%=:\n\t"
            "mbarrier.try_wait.parity.acquire.cta.shared::cta.b64 P1, [%0], %1, 0x989680;\n\t"
            "@P1 bra.uni WAIT_DONE_%=;\n\t"
            "bra.uni WAIT_LOOP_%=;\n\t"
            "WAIT_DONE_%=:\n\t}"
            :: "r"(mbar), "r"(parity) : "memory");
    }
}
__device__ __forceinline__ void bulk_g2s(uint32_t dst, const void* src,
                                         uint32_t bytes, uint32_t mbar) {
    asm volatile(
        "cp.async.bulk.shared::cluster.global.mbarrier::complete_tx::bytes "
        "[%0], [%1], %2, [%3];"
        :: "r"(dst), "l"(src), "r"(bytes), "r"(mbar) : "memory");
}
__device__ __forceinline__ void ldsm4(uint32_t* r, uint32_t addr) {
    asm volatile("ldmatrix.sync.aligned.m8n8.x4.shared.b16 {%0,%1,%2,%3}, [%4];"
        : "=r"(r[0]), "=r"(r[1]), "=r"(r[2]), "=r"(r[3]) : "r"(addr));
}
__device__ __forceinline__ void mma16816(float* d, const uint32_t* a, const uint32_t* b) {
    asm volatile(
        "mma.sync.aligned.m16n8k16.row.col.f32.bf16.bf16.f32 "
        "{%0,%1,%2,%3}, {%4,%5,%6,%7}, {%8,%9}, {%0,%1,%2,%3};"
        : "+f"(d[0]), "+f"(d[1]), "+f"(d[2]), "+f"(d[3])
        : "r"(a[0]), "r"(a[1]), "r"(a[2]), "r"(a[3]), "r"(b[0]), "r"(b[1]));
}

// packed layout helper: element index for (blk128, kc, r, pl, kk)
__device__ __forceinline__ size_t pk_rowseg(int KC, int blk, int kc, int r) {
    return ((size_t)(blk * KC + kc) * 128 + r) * 128;
}
__device__ __forceinline__ int pk_within(int r, int kk) {
    int ch = kk >> 3, w8 = kk & 7;
    return ((ch ^ (r & 7)) << 3) + w8;
}

// ======================= small kernels =======================
__global__ void embed_kernel(const int* __restrict__ tok,
                             const float* __restrict__ wte,
                             const float* __restrict__ wpe,
                             float* __restrict__ h) {
    int bt = blockIdx.x;
    int t  = bt % TT;
    int tk = tok[bt];
    const float* we = wte + (size_t)tk * CC;
    const float* wp = wpe + (size_t)t  * CC;
    float* hr = h + (size_t)bt * CC;
    for (int c = threadIdx.x; c < CC; c += blockDim.x)
        hr[c] = we[c] + wp[c];
}

// LayerNorm producing packed bf16 hi/lo A-operand (KC = CC/64 = 12)
__global__ void ln_pk_kernel(const float* __restrict__ x,
                             const float* __restrict__ gamma,
                             const float* __restrict__ beta,
                             __nv_bfloat16* __restrict__ outpk) {
    int row = blockIdx.x;
    const float* xr = x + (size_t)row * CC;
    __shared__ float red[256];
    int tid = threadIdx.x;

    float s = 0.f;
    for (int c = tid; c < CC; c += 256) s += xr[c];
    red[tid] = s; __syncthreads();
    for (int o = 128; o > 0; o >>= 1) {
        if (tid < o) red[tid] += red[tid + o];
        __syncthreads();
    }
    float mu = red[0] * (1.0f / CC);
    __syncthreads();

    float v = 0.f;
    for (int c = tid; c < CC; c += 256) { float d = xr[c] - mu; v += d * d; }
    red[tid] = v; __syncthreads();
    for (int o = 128; o > 0; o >>= 1) {
        if (tid < o) red[tid] += red[tid + o];
        __syncthreads();
    }
    float rstd = rsqrtf(red[0] * (1.0f / CC) + 1e-5f);

    int blk = row >> 7, r = row & 127;
    for (int c = tid; c < CC; c += 256) {
        float val = (xr[c] - mu) * rstd * gamma[c] + beta[c];
        __nv_bfloat16 hi = __float2bfloat16(val);
        __nv_bfloat16 lo = __float2bfloat16(val - __bfloat162float(hi));
        size_t base = pk_rowseg(12, blk, c >> 6, r);
        int w = pk_within(r, c & 63);
        outpk[base + w]      = hi;
        outpk[base + 64 + w] = lo;
    }
}

// transpose + convert + split weight W[K,N](fp32) -> packed layout
__global__ __launch_bounds__(256)
void pack_w_kernel(const float* __restrict__ W, __nv_bfloat16* __restrict__ Bpk,
                   int K, int N, int n0out) {
    __shared__ float sm[64][65];
    int tid = threadIdx.x;
    int n0 = blockIdx.x * 64;
    int k0 = blockIdx.y * 64;
    int KC = K >> 6;

    for (int idx = tid; idx < 64 * 64; idx += 256) {
        int kr = idx >> 6, nc = idx & 63;
        int gn = n0 + nc;
        sm[kr][nc] = (gn < N) ? W[(size_t)(k0 + kr) * N + gn] : 0.f;
    }
    __syncthreads();

    for (int g = tid; g < 512; g += 256) {
        int n = g >> 3, ch = g & 7;
        int gn = n0out + n0 + n;
        int bn = gn >> 7, r = gn & 127;
        size_t base = pk_rowseg(KC, bn, blockIdx.y, r);
        int w = (ch ^ (r & 7)) << 3;
        union { uint4 v; __nv_bfloat16 b[8]; } uh, ul;
#pragma unroll
        for (int j = 0; j < 8; ++j) {
            float x = sm[ch * 8 + j][n];
            __nv_bfloat16 hi = __float2bfloat16(x);
            uh.b[j] = hi;
            ul.b[j] = __float2bfloat16(x - __bfloat162float(hi));
        }
        *(uint4*)(Bpk + base + w)      = uh.v;
        *(uint4*)(Bpk + base + 64 + w) = ul.v;
    }
}

// ======================= HMMA GEMM (mma.sync bf16 x3 split) =======================
#define EPI_NONE 0
#define EPI_BIAS 1
#define EPI_GELU_PK 2
#define EPI_RES 3

#define STAGES 3
#define STAGE_BYTES 65536   // A 32K | B 32K  (BK=64)
#define HG_SMEM (STAGES * STAGE_BYTES)

template<int EPI>
__global__ __launch_bounds__(256, 1)
void hgemm(const __nv_bfloat16* __restrict__ Apk,
           const __nv_bfloat16* __restrict__ Bpk,
           const float* __restrict__ bias,
           const float* __restrict__ Res,
           float* __restrict__ outf,
           __nv_bfloat16* __restrict__ outpk,
           int N, int K, int Nl) {
    extern __shared__ __align__(1024) char smem[];
    __shared__ __align__(8) uint64_t s_full[STAGES];

    int tid = threadIdx.x;
    int lane = tid & 31, w = tid >> 5;
    int wm = w & 1, wn = w >> 1;      // warp grid 2(M) x 4(N)
    int bm = blockIdx.y, bn = blockIdx.x;
    int KC = K >> 6;
    uint32_t sbase = smem_u32(smem);
    uint32_t mb0 = smem_u32(&s_full[0]);

    if (tid == 0) {
#pragma unroll
        for (int s = 0; s < STAGES; ++s) MBAR_INIT(mb0 + s * 8, 1);
    }
    __syncthreads();

    float acc[4][4][4];
#pragma unroll
    for (int i = 0; i < 4; ++i)
#pragma unroll
        for (int j = 0; j < 4; ++j)
#pragma unroll
            for (int q = 0; q < 4; ++q) acc[i][j][q] = 0.f;

    const int la15 = lane & 15, lahi = lane >> 4;
    const int bmx = lane >> 3;
    const int brow_base = wn * 32 + ((bmx >> 1) << 3) + (lane & 7);
    const int bcs = bmx & 1;

    const int nc = KC;
    const size_t CHUNK = 16384;   // bf16 elements per 32KB block

    if (tid == 0) {
#pragma unroll
        for (int c = 0; c < STAGES - 1; ++c) {
            uint32_t m = mb0 + c * 8;
            MBAR_EXPECT_TX(m, STAGE_BYTES);
            bulk_g2s(sbase + c * STAGE_BYTES,
                     Apk + ((size_t)bm * KC + c) * CHUNK, 32768, m);
            bulk_g2s(sbase + c * STAGE_BYTES + 32768,
                     Bpk + ((size_t)bn * KC + c) * CHUNK, 32768, m);
        }
    }

    for (int c = 0; c < nc; ++c) {
        int s = c % STAGES;
        mbar_wait(mb0 + s * 8, (c / STAGES) & 1);

        if (tid == 0) {
            int cn = c + STAGES - 1;
            if (cn < nc) {
                int sn = cn % STAGES;
                uint32_t m = mb0 + sn * 8;
                MBAR_EXPECT_TX(m, STAGE_BYTES);
                bulk_g2s(sbase + sn * STAGE_BYTES,
                         Apk + ((size_t)bm * KC + cn) * CHUNK, 32768, m);
                bulk_g2s(sbase + sn * STAGE_BYTES + 32768,
                         Bpk + ((size_t)bn * KC + cn) * CHUNK, 32768, m);
            }
        }

        uint32_t Ab = sbase + s * STAGE_BYTES;
        uint32_t Bb = Ab + 32768;

#pragma unroll
        for (int kh = 0; kh < 4; ++kh) {
            uint32_t af[2][4][4];
            uint32_t bf_[2][4][2];
#pragma unroll
            for (int im = 0; im < 4; ++im) {
                int r = wm * 64 + im * 16 + la15;
                int cch = kh * 2 + lahi;
                uint32_t off = (uint32_t)(r * 256 + (((cch ^ (r & 7))) << 4));
                ldsm4(af[0][im], Ab + off);
                ldsm4(af[1][im], Ab + off + 128);
            }
#pragma unroll
            for (int g2 = 0; g2 < 2; ++g2) {
                int nr = brow_base + g2 * 16;
                int cch = kh * 2 + bcs;
                uint32_t off = (uint32_t)(nr * 256 + (((cch ^ (nr & 7))) << 4));
#pragma unroll
                for (int pl = 0; pl < 2; ++pl) {
                    uint32_t t4[4];
                    ldsm4(t4, Bb + off + pl * 128);
                    bf_[pl][g2 * 2][0]     = t4[0];
                    bf_[pl][g2 * 2][1]     = t4[1];
                    bf_[pl][g2 * 2 + 1][0] = t4[2];
                    bf_[pl][g2 * 2 + 1][1] = t4[3];
                }
            }
#pragma unroll
            for (int im = 0; im < 4; ++im)
#pragma unroll
                for (int in_ = 0; in_ < 4; ++in_) {
                    mma16816(acc[im][in_], af[0][im], bf_[0][in_]);
                    mma16816(acc[im][in_], af[0][im], bf_[1][in_]);
                    mma16816(acc[im][in_], af[1][im], bf_[0][in_]);
                }
        }
        __syncthreads();
    }

    // ---------------- epilogue ----------------
    int r0 = bm * 128 + wm * 64 + (lane >> 2);
    int c0base = bn * 128 + wn * 32 + 2 * (lane & 3);
    int KCo = N >> 6;

#pragma unroll
    for (int im = 0; im < 4; ++im) {
#pragma unroll
        for (int half = 0; half < 2; ++half) {
            int row = r0 + im * 16 + half * 8;
#pragma unroll
            for (int in_ = 0; in_ < 4; ++in_) {
                int col = c0base + in_ * 8;
                float v0 = acc[im][in_][half * 2 + 0];
                float v1 = acc[im][in_][half * 2 + 1];
                if (EPI == EPI_NONE) {
                    *(float2*)(outf + (size_t)row * Nl + col) = make_float2(v0, v1);
                } else if (EPI == EPI_RES) {
                    const float* rr = Res + (size_t)row * Nl + col;
                    v0 += bias[col]     + rr[0];
                    v1 += bias[col + 1] + rr[1];
                    *(float2*)(outf + (size_t)row * Nl + col) = make_float2(v0, v1);
                } else if (EPI == EPI_BIAS) {
                    if (col < Nl)     outf[(size_t)row * Nl + col]     = v0 + bias[col];
                    if (col + 1 < Nl) outf[(size_t)row * Nl + col + 1] = v1 + bias[col + 1];
                } else if (EPI == EPI_GELU_PK) {
                    v0 += bias[col];
                    v1 += bias[col + 1];
                    v0 = 0.5f * v0 * (1.0f + erff(v0 * 0.7071067811865476f));
                    v1 = 0.5f * v1 * (1.0f + erff(v1 * 0.7071067811865476f));
                    __nv_bfloat16 h0 = __float2bfloat16(v0);
                    __nv_bfloat16 h1 = __float2bfloat16(v1);
                    __nv_bfloat16 l0 = __float2bfloat16(v0 - __bfloat162float(h0));
                    __nv_bfloat16 l1 = __float2bfloat16(v1 - __bfloat162float(h1));
                    int blk = row >> 7, r = row & 127;
                    size_t base = pk_rowseg(KCo, blk, col >> 6, r);
                    int wi = pk_within(r, col & 63);
                    *(__nv_bfloat162*)(outpk + base + wi) =
                        __nv_bfloat162(h0, h1);
                    *(__nv_bfloat162*)(outpk + base + 64 + wi) =
                        __nv_bfloat162(l0, l1);
                }
            }
        }
    }
}

// ---------------- tiled causal attention: 64 q-rows per block ----------------
// grid (T/64, H, B), 256 threads. Thread = (qr = tid>>2, dg = tid&3).
// Dyn smem: sq | sk | sv | sp, each [64][68] floats.
#define ATT_PAD 68
#define ATT_ROW (64 * ATT_PAD)
#define ATT_SMEM (4 * ATT_ROW * 4)

__global__ __launch_bounds__(256)
void attn_kernel(const float* __restrict__ QKV,
                 __nv_bfloat16* __restrict__ Opk) {
    extern __shared__ float asm_[];
    float* sq = asm_;
    float* sk = asm_ + ATT_ROW;
    float* sv = asm_ + 2 * ATT_ROW;
    float* sp = asm_ + 3 * ATT_ROW;

    int tid = threadIdx.x;
    int q0 = blockIdx.x * 64;
    int hh = blockIdx.y;
    int b  = blockIdx.z;
    int qr = tid >> 2, dg = tid & 3;
    int qg = q0 + qr;

    const float scale = rsqrtf((float)CC);

    // load Q tile: 64 rows x 64 cols
    {
        int r = tid >> 4, c4 = (tid & 15) * 4;
#pragma unroll
        for (int it = 0; it < 4; ++it, r += 16) {
            *(float4*)&sq[r * ATT_PAD + c4] =
                *(const float4*)(QKV + ((size_t)(b * TT + q0 + r)) * NQKV + hh * DD + c4);
        }
    }

    float m = -INFINITY, l = 0.f;
    float acc[16];
#pragma unroll
    for (int i = 0; i < 16; ++i) acc[i] = 0.f;

    for (int j0 = 0; j0 <= q0; j0 += 64) {
        __syncthreads();   // prior PV reads done before overwriting sk/sv
        // load K and V tiles
        {
            int r = tid >> 4, c4 = (tid & 15) * 4;
#pragma unroll
            for (int it = 0; it < 4; ++it, r += 16) {
                size_t rb = ((size_t)(b * TT + j0 + r)) * NQKV + hh * DD + c4;
                *(float4*)&sk[r * ATT_PAD + c4] = *(const float4*)(QKV + rb + CC);
                *(float4*)&sv[r * ATT_PAD + c4] = *(const float4*)(QKV + rb + 2 * CC);
            }
        }
        __syncthreads();

        // scores: thread computes j = jj*4 + dg, jj = 0..15
        float s[16];
#pragma unroll
        for (int jj = 0; jj < 16; ++jj) s[jj] = 0.f;
        const float* qrow = sq + qr * ATT_PAD;
#pragma unroll
        for (int k4 = 0; k4 < 16; ++k4) {
            float4 qv = *(const float4*)(qrow + k4 * 4);
#pragma unroll
            for (int jj = 0; jj < 16; ++jj) {
                int j = jj * 4 + dg;
                float4 kv = *(const float4*)(sk + j * ATT_PAD + k4 * 4);
                s[jj] = fmaf(qv.x, kv.x, s[jj]);
                s[jj] = fmaf(qv.y, kv.y, s[jj]);
                s[jj] = fmaf(qv.z, kv.z, s[jj]);
                s[jj] = fmaf(qv.w, kv.w, s[jj]);
            }
        }

        float tmax = -INFINITY;
#pragma unroll
        for (int jj = 0; jj < 16; ++jj) {
            int j = jj * 4 + dg;
            s[jj] = (j0 + j <= qg) ? s[jj] * scale : -INFINITY;
            tmax = fmaxf(tmax, s[jj]);
        }
        tmax = fmaxf(tmax, __shfl_xor_sync(0xFFFFFFFF, tmax, 1));
        tmax = fmaxf(tmax, __shfl_xor_sync(0xFFFFFFFF, tmax, 2));

        float newm = fmaxf(m, tmax);
        float corr = __expf(m - newm);
        float lp = 0.f;
#pragma unroll
        for (int jj = 0; jj < 16; ++jj) {
            int j = jj * 4 + dg;
            float p = __expf(s[jj] - newm);
            sp[qr * ATT_PAD + j] = p;
            lp += p;
        }
        lp += __shfl_xor_sync(0xFFFFFFFF, lp, 1);
        lp += __shfl_xor_sync(0xFFFFFFFF, lp, 2);
        l = l * corr + lp;
        m = newm;
#pragma unroll
        for (int i = 0; i < 16; ++i) acc[i] *= corr;

        __syncthreads();

        // P @ V: thread accumulates d = dg*16 .. dg*16+15
        const float* prow = sp + qr * ATT_PAD;
#pragma unroll 8
        for (int j = 0; j < 64; ++j) {
            float pj = prow[j];
            const float* vrow = sv + j * ATT_PAD + dg * 16;
            float4 v0 = *(const float4*)(vrow);
            float4 v1 = *(const float4*)(vrow + 4);
            float4 v2 = *(const float4*)(vrow + 8);
            float4 v3 = *(const float4*)(vrow + 12);
            acc[0]  = fmaf(pj, v0.x, acc[0]);  acc[1]  = fmaf(pj, v0.y, acc[1]);
            acc[2]  = fmaf(pj, v0.z, acc[2]);  acc[3]  = fmaf(pj, v0.w, acc[3]);
            acc[4]  = fmaf(pj, v1.x, acc[4]);  acc[5]  = fmaf(pj, v1.y, acc[5]);
            acc[6]  = fmaf(pj, v1.z, acc[6]);  acc[7]  = fmaf(pj, v1.w, acc[7]);
            acc[8]  = fmaf(pj, v2.x, acc[8]);  acc[9]  = fmaf(pj, v2.y, acc[9]);
            acc[10] = fmaf(pj, v2.z, acc[10]); acc[11] = fmaf(pj, v2.w, acc[11]);
            acc[12] = fmaf(pj, v3.x, acc[12]); acc[13] = fmaf(pj, v3.y, acc[13]);
            acc[14] = fmaf(pj, v3.z, acc[14]); acc[15] = fmaf(pj, v3.w, acc[15]);
        }
    }

    // write packed bf16 hi/lo output
    float inv = 1.0f / l;
    int rowg = b * TT + qg;
    int blk = rowg >> 7, r = rowg & 127;
    size_t base = pk_rowseg(12, blk, hh, r);   // DD==64 so kc == hh
#pragma unroll
    for (int dd = 0; dd < 16; dd += 2) {
        int d = dg * 16 + dd;
        float v0 = acc[dd] * inv;
        float v1 = acc[dd + 1] * inv;
        __nv_bfloat16 h0 = __float2bfloat16(v0);
        __nv_bfloat16 h1 = __float2bfloat16(v1);
        __nv_bfloat16 l0 = __float2bfloat16(v0 - __bfloat162float(h0));
        __nv_bfloat16 l1 = __float2bfloat16(v1 - __bfloat162float(h1));
        int wi = pk_within(r, d);
        *(__nv_bfloat162*)(Opk + base + wi)      = __nv_bfloat162(h0, h1);
        *(__nv_bfloat162*)(Opk + base + 64 + wi) = __nv_bfloat162(l0, l1);
    }
}

// ======================= launch =======================
extern "C" void kernel_launch(void* const* d_in, const int* in_sizes, int n_in,
                              void* d_out, int out_size) {
    const int*   tokens = (const int*)  d_in[0];
    const float* wte    = (const float*)d_in[1];
    const float* wpe    = (const float*)d_in[2];
    const float* Wq     = (const float*)d_in[3];
    const float* Wk     = (const float*)d_in[4];
    const float* Wv     = (const float*)d_in[5];
    const float* Wo     = (const float*)d_in[6];
    const float* bo     = (const float*)d_in[7];
    const float* ln1g   = (const float*)d_in[8];
    const float* ln1b   = (const float*)d_in[9];
    const float* ln2g   = (const float*)d_in[10];
    const float* ln2b   = (const float*)d_in[11];
    const float* W1     = (const float*)d_in[12];
    const float* b1     = (const float*)d_in[13];
    const float* W2     = (const float*)d_in[14];
    const float* b2     = (const float*)d_in[15];
    const float* lnfg   = (const float*)d_in[16];
    const float* lnfb   = (const float*)d_in[17];
    const float* Wh     = (const float*)d_in[18];
    const float* bh     = (const float*)d_in[19];
    float* out = (float*)d_out;

    static bool attrs_set = false;
    if (!attrs_set) {
        cudaFuncSetAttribute(hgemm<EPI_NONE>,    cudaFuncAttributeMaxDynamicSharedMemorySize, HG_SMEM);
        cudaFuncSetAttribute(hgemm<EPI_BIAS>,    cudaFuncAttributeMaxDynamicSharedMemorySize, HG_SMEM);
        cudaFuncSetAttribute(hgemm<EPI_GELU_PK>, cudaFuncAttributeMaxDynamicSharedMemorySize, HG_SMEM);
        cudaFuncSetAttribute(hgemm<EPI_RES>,     cudaFuncAttributeMaxDynamicSharedMemorySize, HG_SMEM);
        cudaFuncSetAttribute(attn_kernel,        cudaFuncAttributeMaxDynamicSharedMemorySize, ATT_SMEM);
        attrs_set = true;
    }

    float *h, *qkv;
    __nv_bfloat16 *xpk, *opk, *mpk, *wqkvpk, *wopk, *w1pk, *w2pk, *whpk;
    cudaGetSymbolAddress((void**)&h,      g_h);
    cudaGetSymbolAddress((void**)&qkv,    g_qkv);
    cudaGetSymbolAddress((void**)&xpk,    g_xpk);
    cudaGetSymbolAddress((void**)&opk,    g_opk);
    cudaGetSymbolAddress((void**)&mpk,    g_mpk);
    cudaGetSymbolAddress((void**)&wqkvpk, g_wqkvpk);
    cudaGetSymbolAddress((void**)&wopk,   g_wopk);
    cudaGetSymbolAddress((void**)&w1pk,   g_w1pk);
    cudaGetSymbolAddress((void**)&w2pk,   g_w2pk);
    cudaGetSymbolAddress((void**)&whpk,   g_whpk);

    dim3 gQKV(NQKV / 128, MM / 128);   // (18, 32)
    dim3 gC(CC / 128, MM / 128);       // (6, 32)
    dim3 gF(FF / 128, MM / 128);       // (24, 32)
    dim3 gV(VPAD / 128, MM / 128);     // (393, 32)

    dim3 pCC(12, 12);
    dim3 pW1(48, 12);
    dim3 pW2(12, 48);
    dim3 pWh(786, 12);

    embed_kernel<<<MM, 256>>>(tokens, wte, wpe, h);
    pack_w_kernel<<<pWh, 256>>>(Wh, whpk, CC, VV, 0);

    for (int l = 0; l < LL; l++) {
        pack_w_kernel<<<pCC, 256>>>(Wq + (size_t)l * CC * CC, wqkvpk, CC, CC, 0);
        pack_w_kernel<<<pCC, 256>>>(Wk + (size_t)l * CC * CC, wqkvpk, CC, CC, 768);
        pack_w_kernel<<<pCC, 256>>>(Wv + (size_t)l * CC * CC, wqkvpk, CC, CC, 1536);
        pack_w_kernel<<<pCC, 256>>>(Wo + (size_t)l * CC * CC, wopk, CC, CC, 0);
        pack_w_kernel<<<pW1, 256>>>(W1 + (size_t)l * CC * FF, w1pk, CC, FF, 0);
        pack_w_kernel<<<pW2, 256>>>(W2 + (size_t)l * FF * CC, w2pk, FF, CC, 0);

        ln_pk_kernel<<<MM, 256>>>(h, ln1g + l * CC, ln1b + l * CC, xpk);
        hgemm<EPI_NONE><<<gQKV, 256, HG_SMEM>>>(xpk, wqkvpk, nullptr, nullptr,
                                                qkv, nullptr, NQKV, CC, NQKV);

        attn_kernel<<<dim3(TT / 64, HH, BB), 256, ATT_SMEM>>>(qkv, opk);

        hgemm<EPI_RES><<<gC, 256, HG_SMEM>>>(opk, wopk, bo + l * CC, h,
                                             h, nullptr, CC, CC, CC);

        ln_pk_kernel<<<MM, 256>>>(h, ln2g + l * CC, ln2b + l * CC, xpk);
        hgemm<EPI_GELU_PK><<<gF, 256, HG_SMEM>>>(xpk, w1pk, b1 + l * FF, nullptr,
                                                 nullptr, mpk, FF, CC, FF);
        hgemm<EPI_RES><<<gC, 256, HG_SMEM>>>(mpk, w2pk, b2 + l * CC, h,
                                             h, nullptr, CC, FF, CC);
    }

    ln_pk_kernel<<<MM, 256>>>(h, lnfg, lnfb, xpk);
    hgemm<EPI_BIAS><<<gV, 256, HG_SMEM>>>(xpk, whpk, bh, nullptr,
                                          out, nullptr, VPAD, CC, VV);
}